// round 9
// baseline (speedup 1.0000x reference)
#include <cuda_runtime.h>
#include <cuda_fp16.h>
#include <cstdint>
#include <math.h>

#define BB 2
#define NN 2048
#define DD 1024
#define HH 8
#define QH_ 16
#define DH_ 64
#define MM (BB*NN)

// ---------------- scratch ----------------------------------------------------
__device__ __half g_xh [MM*DD];            // rmsnorm(x), fp16 [4096][1024]
__device__ __half g_w  [2*DD*DD];          // [Wq^T ; Wkv^T] fp16 [2048][1024]
__device__ __half g_wo [DD*HH*DH_];        // Wout^T fp16 [1024][512]
__device__ __half g_qh [BB*QH_*NN*DH_];    // normalized q fp16 [b][qh][n][dh]
__device__ __half g_kh [BB*HH*NN*DH_];     // normalized k fp16 [b][h][n][dh]
__device__ __half g_vh [BB*HH*NN*DH_];     // v fp16           [b][h][n][dh]
__device__ __half g_ah [MM*HH*DH_];        // group-summed attn out fp16 [4096][512]

// ---------------- mma / ldmatrix / cp.async helpers ---------------------------
__device__ __forceinline__ void ldsm4(unsigned& r0, unsigned& r1, unsigned& r2,
                                      unsigned& r3, unsigned addr) {
    asm volatile("ldmatrix.sync.aligned.m8n8.x4.shared.b16 {%0,%1,%2,%3}, [%4];"
                 : "=r"(r0), "=r"(r1), "=r"(r2), "=r"(r3) : "r"(addr));
}
__device__ __forceinline__ void ldsm4t(unsigned& r0, unsigned& r1, unsigned& r2,
                                       unsigned& r3, unsigned addr) {
    asm volatile("ldmatrix.sync.aligned.m8n8.x4.trans.shared.b16 {%0,%1,%2,%3}, [%4];"
                 : "=r"(r0), "=r"(r1), "=r"(r2), "=r"(r3) : "r"(addr));
}
__device__ __forceinline__ void mma16816(float* c, const unsigned* a,
                                         unsigned b0, unsigned b1) {
    asm volatile(
        "mma.sync.aligned.m16n8k16.row.col.f32.f16.f16.f32 "
        "{%0,%1,%2,%3},{%4,%5,%6,%7},{%8,%9},{%0,%1,%2,%3};"
        : "+f"(c[0]), "+f"(c[1]), "+f"(c[2]), "+f"(c[3])
        : "r"(a[0]), "r"(a[1]), "r"(a[2]), "r"(a[3]), "r"(b0), "r"(b1));
}
__device__ __forceinline__ void cpa16(unsigned dst, const void* src) {
    asm volatile("cp.async.cg.shared.global [%0], [%1], 16;" :: "r"(dst), "l"(src));
}
#define CP_COMMIT() asm volatile("cp.async.commit_group;")
#define CP_WAIT(n)  asm volatile("cp.async.wait_group %0;" :: "n"(n))

// ---------------- rmsnorm -> fp16, one warp per row ---------------------------
__global__ void rmsnorm_kernel(const float* __restrict__ x,
                               const float* __restrict__ w) {
    const int row = blockIdx.x * 8 + (threadIdx.x >> 5);
    const int lane = threadIdx.x & 31;
    const float4* xr = (const float4*)(x + (size_t)row * DD);
    float4 xv[8];
    float ss = 0.f;
    #pragma unroll
    for (int i = 0; i < 8; i++) {
        xv[i] = xr[lane + 32 * i];
        ss += xv[i].x * xv[i].x + xv[i].y * xv[i].y
            + xv[i].z * xv[i].z + xv[i].w * xv[i].w;
    }
    #pragma unroll
    for (int o = 16; o; o >>= 1) ss += __shfl_xor_sync(~0u, ss, o);
    const float r = rsqrtf(ss * (1.0f / DD) + 1.1920929e-07f);
    const float4* wr = (const float4*)w;
    uint2* yr = (uint2*)(g_xh + (size_t)row * DD);
    #pragma unroll
    for (int i = 0; i < 8; i++) {
        float4 wv = wr[lane + 32 * i];
        __half2 h0 = __floats2half2_rn(xv[i].x * r * wv.x, xv[i].y * r * wv.y);
        __half2 h1 = __floats2half2_rn(xv[i].z * r * wv.z, xv[i].w * r * wv.w);
        uint2 u;
        u.x = *(unsigned*)&h0;
        u.y = *(unsigned*)&h1;
        yr[lane + 32 * i] = u;
    }
}

// ---------------- weight transpose+convert -----------------------------------
__global__ void wtransqkv_kernel(const float* __restrict__ Wq,
                                 const float* __restrict__ Wkv) {
    __shared__ float t[32][33];
    const float* W = blockIdx.z ? Wkv : Wq;
    __half* Wt = g_w + (size_t)blockIdx.z * DD * DD;
    int n0 = blockIdx.x * 32, k0 = blockIdx.y * 32;
    int x = threadIdx.x, y = threadIdx.y;
    #pragma unroll
    for (int i = 0; i < 32; i += 8)
        t[y + i][x] = W[(size_t)(k0 + y + i) * DD + n0 + x];
    __syncthreads();
    #pragma unroll
    for (int i = 0; i < 32; i += 8)
        Wt[(size_t)(n0 + y + i) * DD + k0 + x] = __float2half(t[x][y + i]);
}
__global__ void wtrans_kernel(const float* __restrict__ W, __half* __restrict__ Wt,
                              int K, int N) {
    __shared__ float t[32][33];
    int n0 = blockIdx.x * 32, k0 = blockIdx.y * 32;
    int x = threadIdx.x, y = threadIdx.y;
    #pragma unroll
    for (int i = 0; i < 32; i += 8)
        t[y + i][x] = W[(size_t)(k0 + y + i) * N + n0 + x];
    __syncthreads();
    #pragma unroll
    for (int i = 0; i < 32; i += 8)
        Wt[(size_t)(n0 + y + i) * K + k0 + x] = __float2half(t[x][y + i]);
}

#define ASTR 40
#define SST  5120                 // halves per matrix-stage (128*40)
#define SSTB (SST*2)              // bytes per matrix-stage
#define BBASE (3*SST)             // B region starts after 3 A stages (halves)
#define GEMM_SMEM (6*SST*2)       // 61440 bytes

// ---------------- fused QKV GEMM + per-head norm epilogue (3-stage) ----------
__global__ void __launch_bounds__(256, 2)
qkv_gemm_kernel(const __half* __restrict__ A, const __half* __restrict__ Bt,
                const float* __restrict__ q_gamma,
                const float* __restrict__ k_gamma) {
    extern __shared__ __half shg[];
    const int K = 1024;
    const int tid = threadIdx.x;
    const int lane = tid & 31;
    const int warp = tid >> 5;
    const int wm = (warp >> 1) << 5;
    const int wn = (warp & 1) << 6;
    const int bm = blockIdx.y << 7;
    const int bn = blockIdx.x << 7;

    const int lr = tid >> 2;
    const int lg = (tid & 3) << 3;
    const __half* Ag = A + (size_t)(bm + lr) * K + lg;
    const __half* Bg = Bt + (size_t)(bn + lr) * K + lg;
    const size_t rowskip = (size_t)64 * K;

    unsigned sb;
    asm("{ .reg .u64 t; cvta.to.shared.u64 t, %1; cvt.u32.u64 %0, t; }"
        : "=r"(sb) : "l"(shg));
    const unsigned stA0 = sb + (unsigned)(lr * ASTR + lg) * 2u;
    const unsigned stA1 = sb + (unsigned)((lr + 64) * ASTR + lg) * 2u;
    const unsigned stB0 = stA0 + (unsigned)BBASE * 2u;
    const unsigned stB1 = stA1 + (unsigned)BBASE * 2u;

    const int aRow = wm + (lane & 15);
    const int aK   = (lane >> 4) << 3;
    const int bRow = wn + (lane & 7) + ((lane >> 4) << 3);
    const int bK   = ((lane >> 3) & 1) << 3;
    const unsigned ldA = sb + (unsigned)(aRow * ASTR + aK) * 2u;
    const unsigned ldB = sb + (unsigned)(BBASE + bRow * ASTR + bK) * 2u;

    float acc[2][8][4];
    #pragma unroll
    for (int i = 0; i < 2; i++) {
        #pragma unroll
        for (int j = 0; j < 8; j++) {
            #pragma unroll
            for (int q = 0; q < 4; q++) acc[i][j][q] = 0.f;
        }
    }

    // prologue: chunks 0,1 -> stages 0,1
    cpa16(stA0, Ag);
    cpa16(stA1, Ag + rowskip);
    cpa16(stB0, Bg);
    cpa16(stB1, Bg + rowskip);
    CP_COMMIT();
    cpa16(stA0 + SSTB, Ag + 32);
    cpa16(stA1 + SSTB, Ag + rowskip + 32);
    cpa16(stB0 + SSTB, Bg + 32);
    cpa16(stB1 + SSTB, Bg + rowskip + 32);
    CP_COMMIT();

    const int nch = K >> 5;
    int stg = 0, pf = 2;
    for (int c = 0; c < nch; c++) {
        if (c < nch - 1) { CP_WAIT(1); } else { CP_WAIT(0); }
        __syncthreads();
        if (c + 2 < nch) {
            const unsigned nb = (unsigned)pf * SSTB;
            const __half* An = Ag + (c + 2) * 32;
            const __half* Bn = Bg + (c + 2) * 32;
            cpa16(stA0 + nb, An);
            cpa16(stA1 + nb, An + rowskip);
            cpa16(stB0 + nb, Bn);
            cpa16(stB1 + nb, Bn + rowskip);
            CP_COMMIT();
        }
        const unsigned bo = (unsigned)stg * SSTB;
        #pragma unroll
        for (int ks = 0; ks < 2; ks++) {
            unsigned a0r[4], a1r[4], b[4][4];
            ldsm4(a0r[0], a0r[1], a0r[2], a0r[3], ldA + bo + ks * 32);
            ldsm4(a1r[0], a1r[1], a1r[2], a1r[3],
                  ldA + bo + 16 * ASTR * 2 + ks * 32);
            #pragma unroll
            for (int p = 0; p < 4; p++)
                ldsm4(b[p][0], b[p][1], b[p][2], b[p][3],
                      ldB + bo + (unsigned)(p * 16 * ASTR * 2) + ks * 32);
            #pragma unroll
            for (int p = 0; p < 4; p++) {
                mma16816(acc[0][2 * p],     a0r, b[p][0], b[p][1]);
                mma16816(acc[0][2 * p + 1], a0r, b[p][2], b[p][3]);
                mma16816(acc[1][2 * p],     a1r, b[p][0], b[p][1]);
                mma16816(acc[1][2 * p + 1], a1r, b[p][2], b[p][3]);
            }
        }
        stg = (stg + 1 == 3) ? 0 : stg + 1;
        pf  = (pf + 1 == 3) ? 0 : pf + 1;
    }

    // ---- fused epilogue: per-head l2norm / convert ----
    const int er = lane >> 2;
    const int ec = (lane & 3) << 1;
    const int colbase = bn + wn;
    int head, nh;
    __half* darr;
    const float* gp;
    if (colbase < 1024)      { head = colbase >> 6;          darr = g_qh; gp = q_gamma + head * 64; nh = 16; }
    else if (colbase < 1536) { head = (colbase - 1024) >> 6; darr = g_kh; gp = k_gamma + head * 64; nh = 8; }
    else                     { head = (colbase - 1536) >> 6; darr = g_vh; gp = nullptr;             nh = 8; }

    float gs[8][2];
    #pragma unroll
    for (int nt = 0; nt < 8; nt++) {
        if (gp) {
            gs[nt][0] = (gp[nt * 8 + ec] + 1.f) * 8.f;
            gs[nt][1] = (gp[nt * 8 + ec + 1] + 1.f) * 8.f;
        } else {
            gs[nt][0] = 1.f;
            gs[nt][1] = 1.f;
        }
    }

    #pragma unroll
    for (int mt = 0; mt < 2; mt++) {
        #pragma unroll
        for (int rh = 0; rh < 2; rh++) {
            float s = 0.f;
            #pragma unroll
            for (int nt = 0; nt < 8; nt++) {
                float v0 = acc[mt][nt][2 * rh];
                float v1 = acc[mt][nt][2 * rh + 1];
                s = fmaf(v0, v0, fmaf(v1, v1, s));
            }
            s += __shfl_xor_sync(~0u, s, 1);
            s += __shfl_xor_sync(~0u, s, 2);
            float iv = gp ? (1.0f / fmaxf(sqrtf(s), 1e-12f)) : 1.0f;

            int m = bm + wm + mt * 16 + rh * 8 + er;
            int b = m >> 11, n = m & (NN - 1);
            __half* drow = darr + (((size_t)(b * nh + head)) * NN + n) * DH_;
            #pragma unroll
            for (int nt = 0; nt < 8; nt++) {
                float o0 = acc[mt][nt][2 * rh] * iv * gs[nt][0];
                float o1 = acc[mt][nt][2 * rh + 1] * iv * gs[nt][1];
                *(__half2*)(drow + nt * 8 + ec) = __floats2half2_rn(o0, o1);
            }
        }
    }
}

// ---------------- out-proj GEMM (3-stage cp.async) ----------------------------
__global__ void __launch_bounds__(256, 2)
hgemm_kernel(const __half* __restrict__ A, const __half* __restrict__ Bt,
             float* __restrict__ C, int K) {
    extern __shared__ __half shg[];
    const int tid = threadIdx.x;
    const int lane = tid & 31;
    const int warp = tid >> 5;
    const int wm = (warp >> 1) << 5;
    const int wn = (warp & 1) << 6;
    const int bm = blockIdx.y << 7;
    const int bn = blockIdx.x << 7;

    const int lr = tid >> 2;
    const int lg = (tid & 3) << 3;
    const __half* Ag = A + (size_t)(bm + lr) * K + lg;
    const __half* Bg = Bt + (size_t)(bn + lr) * K + lg;
    const size_t rowskip = (size_t)64 * K;

    unsigned sb;
    asm("{ .reg .u64 t; cvta.to.shared.u64 t, %1; cvt.u32.u64 %0, t; }"
        : "=r"(sb) : "l"(shg));
    const unsigned stA0 = sb + (unsigned)(lr * ASTR + lg) * 2u;
    const unsigned stA1 = sb + (unsigned)((lr + 64) * ASTR + lg) * 2u;
    const unsigned stB0 = stA0 + (unsigned)BBASE * 2u;
    const unsigned stB1 = stA1 + (unsigned)BBASE * 2u;

    const int aRow = wm + (lane & 15);
    const int aK   = (lane >> 4) << 3;
    const int bRow = wn + (lane & 7) + ((lane >> 4) << 3);
    const int bK   = ((lane >> 3) & 1) << 3;
    const unsigned ldA = sb + (unsigned)(aRow * ASTR + aK) * 2u;
    const unsigned ldB = sb + (unsigned)(BBASE + bRow * ASTR + bK) * 2u;

    float acc[2][8][4];
    #pragma unroll
    for (int i = 0; i < 2; i++) {
        #pragma unroll
        for (int j = 0; j < 8; j++) {
            #pragma unroll
            for (int q = 0; q < 4; q++) acc[i][j][q] = 0.f;
        }
    }

    cpa16(stA0, Ag);
    cpa16(stA1, Ag + rowskip);
    cpa16(stB0, Bg);
    cpa16(stB1, Bg + rowskip);
    CP_COMMIT();
    cpa16(stA0 + SSTB, Ag + 32);
    cpa16(stA1 + SSTB, Ag + rowskip + 32);
    cpa16(stB0 + SSTB, Bg + 32);
    cpa16(stB1 + SSTB, Bg + rowskip + 32);
    CP_COMMIT();

    const int nch = K >> 5;
    int stg = 0, pf = 2;
    for (int c = 0; c < nch; c++) {
        if (c < nch - 1) { CP_WAIT(1); } else { CP_WAIT(0); }
        __syncthreads();
        if (c + 2 < nch) {
            const unsigned nb = (unsigned)pf * SSTB;
            const __half* An = Ag + (c + 2) * 32;
            const __half* Bn = Bg + (c + 2) * 32;
            cpa16(stA0 + nb, An);
            cpa16(stA1 + nb, An + rowskip);
            cpa16(stB0 + nb, Bn);
            cpa16(stB1 + nb, Bn + rowskip);
            CP_COMMIT();
        }
        const unsigned bo = (unsigned)stg * SSTB;
        #pragma unroll
        for (int ks = 0; ks < 2; ks++) {
            unsigned a0r[4], a1r[4], b[4][4];
            ldsm4(a0r[0], a0r[1], a0r[2], a0r[3], ldA + bo + ks * 32);
            ldsm4(a1r[0], a1r[1], a1r[2], a1r[3],
                  ldA + bo + 16 * ASTR * 2 + ks * 32);
            #pragma unroll
            for (int p = 0; p < 4; p++)
                ldsm4(b[p][0], b[p][1], b[p][2], b[p][3],
                      ldB + bo + (unsigned)(p * 16 * ASTR * 2) + ks * 32);
            #pragma unroll
            for (int p = 0; p < 4; p++) {
                mma16816(acc[0][2 * p],     a0r, b[p][0], b[p][1]);
                mma16816(acc[0][2 * p + 1], a0r, b[p][2], b[p][3]);
                mma16816(acc[1][2 * p],     a1r, b[p][0], b[p][1]);
                mma16816(acc[1][2 * p + 1], a1r, b[p][2], b[p][3]);
            }
        }
        stg = (stg + 1 == 3) ? 0 : stg + 1;
        pf  = (pf + 1 == 3) ? 0 : pf + 1;
    }

    const int er = lane >> 2;
    const int ec = (lane & 3) << 1;
    #pragma unroll
    for (int mt = 0; mt < 2; mt++) {
        #pragma unroll
        for (int nt = 0; nt < 8; nt++) {
            int r0 = bm + wm + mt * 16 + er;
            int c0 = bn + wn + nt * 8 + ec;
            *(float2*)&C[(size_t)r0 * 1024 + c0] =
                make_float2(acc[mt][nt][0], acc[mt][nt][1]);
            *(float2*)&C[(size_t)(r0 + 8) * 1024 + c0] =
                make_float2(acc[mt][nt][2], acc[mt][nt][3]);
        }
    }
}

// ---------------- tensor-core flash attention (R8 version, unchanged) ---------
#define TSTR 72
#define QOFF 0
#define KOFF 9216
#define VOFF 18432
#define ATT_SMEM (27648 * 2)

__global__ void __launch_bounds__(256) attn_kernel() {
    extern __shared__ __half sh[];
    float* Obuf = (float*)(sh + KOFF);
    const int qt = 31 - blockIdx.x;          // heavy tiles first
    const int h = blockIdx.y, b = blockIdx.z;
    const int tid = threadIdx.x, lane = tid & 31, warp = tid >> 5;
    const int hw = warp >> 2;
    const int wr = (warp & 3) << 4;
    const int er = lane >> 2, ec = (lane & 3) << 1;

    unsigned sb;
    asm("{ .reg .u64 t; cvta.to.shared.u64 t, %1; cvt.u32.u64 %0, t; }"
        : "=r"(sb) : "l"(sh));

    const __half* qg = g_qh + (((size_t)(b * QH_ + 2 * h)) * NN + qt * 64) * DH_;
    const __half* kg = g_kh + ((size_t)(b * HH + h)) * NN * DH_;
    const __half* vg = g_vh + ((size_t)(b * HH + h)) * NN * DH_;

    #pragma unroll
    for (int it = 0; it < 4; it++) {
        int u = tid + it * 256;
        int head = u >> 9, row = (u >> 3) & 63, cg = u & 7;
        cpa16(sb + (unsigned)(QOFF + head * 4608 + row * TSTR + cg * 8) * 2u,
              qg + (size_t)head * NN * DH_ + row * 64 + cg * 8);
    }
    {
        int row = tid >> 3, cg = tid & 7;
        #pragma unroll
        for (int it = 0; it < 2; it++) {
            int rr = row + it * 32;
            size_t go = (size_t)rr * 64 + cg * 8;
            cpa16(sb + (unsigned)(KOFF + rr * TSTR + cg * 8) * 2u, kg + go);
            cpa16(sb + (unsigned)(VOFF + rr * TSTR + cg * 8) * 2u, vg + go);
        }
    }
    CP_COMMIT();

    const unsigned ldQ = sb + (unsigned)(QOFF + hw * 4608 + (wr + (lane & 15)) * TSTR
                                         + ((lane >> 4) << 3)) * 2u;
    const unsigned ldK = sb + (unsigned)(KOFF + ((lane & 7) + ((lane >> 4) << 3)) * TSTR
                                         + (((lane >> 3) & 1) << 3)) * 2u;
    const unsigned ldV = sb + (unsigned)(VOFF + ((lane & 7) + (((lane >> 3) & 1) << 3)) * TSTR
                                         + ((lane >> 4) << 3)) * 2u;

    float ofrag[8][4];
    float mrow[2] = {-3.0e38f, -3.0e38f};
    float lrow[2] = {0.f, 0.f};
    #pragma unroll
    for (int nt = 0; nt < 8; nt++) {
        #pragma unroll
        for (int q = 0; q < 4; q++) ofrag[nt][q] = 0.f;
    }

    for (int jt = 0; jt <= qt; jt++) {
        const unsigned bufb = (unsigned)(jt & 1) * 9216u;
        if (jt < qt) {
            const unsigned nb = (unsigned)((jt + 1) & 1) * 4608u;
            int row = tid >> 3, cg = tid & 7;
            #pragma unroll
            for (int it = 0; it < 2; it++) {
                int rr = row + it * 32;
                size_t go = (size_t)((jt + 1) * 64 + rr) * 64 + cg * 8;
                cpa16(sb + (KOFF + nb + rr * TSTR + cg * 8) * 2u, kg + go);
                cpa16(sb + (VOFF + nb + rr * TSTR + cg * 8) * 2u, vg + go);
            }
            CP_COMMIT();
            CP_WAIT(1);
        } else {
            CP_WAIT(0);
        }
        __syncthreads();

        // ---- S = Q @ K^T ----
        float sfrag[8][4];
        #pragma unroll
        for (int nt = 0; nt < 8; nt++) {
            #pragma unroll
            for (int q = 0; q < 4; q++) sfrag[nt][q] = 0.f;
        }
        #pragma unroll
        for (int ks = 0; ks < 4; ks++) {
            unsigned a[4];
            ldsm4(a[0], a[1], a[2], a[3], ldQ + ks * 32);
            #pragma unroll
            for (int np = 0; np < 4; np++) {
                unsigned bf[4];
                ldsm4(bf[0], bf[1], bf[2], bf[3],
                      ldK + bufb + (unsigned)(np * 16 * TSTR * 2) + ks * 32);
                mma16816(sfrag[2 * np],     a, bf[0], bf[1]);
                mma16816(sfrag[2 * np + 1], a, bf[2], bf[3]);
            }
        }

        // ---- softcap + mask + online softmax ----
        const bool diag = (jt == qt);
        #pragma unroll
        for (int r2 = 0; r2 < 2; r2++) {
            const int ig = wr + er + 8 * r2;
            float mx = -3.0e38f;
            #pragma unroll
            for (int nt = 0; nt < 8; nt++) {
                #pragma unroll
                for (int c = 0; c < 2; c++) {
                    float s = sfrag[nt][2 * r2 + c];
                    float e = __expf(s * 0.04f);
                    float x = (1.f - __fdividef(2.f, e + 1.f)) * 6.25f;
                    if (diag && (nt * 8 + ec + c > ig)) x = -3.0e38f;
                    sfrag[nt][2 * r2 + c] = x;
                    mx = fmaxf(mx, x);
                }
            }
            mx = fmaxf(mx, __shfl_xor_sync(~0u, mx, 1));
            mx = fmaxf(mx, __shfl_xor_sync(~0u, mx, 2));
            float mn = fmaxf(mrow[r2], mx);
            float alpha = __expf(mrow[r2] - mn);
            mrow[r2] = mn;
            float ps = 0.f;
            #pragma unroll
            for (int nt = 0; nt < 8; nt++) {
                #pragma unroll
                for (int c = 0; c < 2; c++) {
                    float p = __expf(sfrag[nt][2 * r2 + c] - mn);
                    sfrag[nt][2 * r2 + c] = p;
                    ps += p;
                }
            }
            ps += __shfl_xor_sync(~0u, ps, 1);
            ps += __shfl_xor_sync(~0u, ps, 2);
            lrow[r2] = lrow[r2] * alpha + ps;
            #pragma unroll
            for (int nt = 0; nt < 8; nt++) {
                ofrag[nt][2 * r2]     *= alpha;
                ofrag[nt][2 * r2 + 1] *= alpha;
            }
        }

        unsigned pa[8][2];
        #pragma unroll
        for (int nt = 0; nt < 8; nt++) {
            __half2 h0 = __floats2half2_rn(sfrag[nt][0], sfrag[nt][1]);
            __half2 h1 = __floats2half2_rn(sfrag[nt][2], sfrag[nt][3]);
            pa[nt][0] = *(unsigned*)&h0;
            pa[nt][1] = *(unsigned*)&h1;
        }

        // ---- O += P @ V ----
        #pragma unroll
        for (int kv = 0; kv < 4; kv++) {
            unsigned a[4] = {pa[2 * kv][0], pa[2 * kv][1],
                             pa[2 * kv + 1][0], pa[2 * kv + 1][1]};
            #pragma unroll
            for (int np = 0; np < 4; np++) {
                unsigned bf[4];
                ldsm4t(bf[0], bf[1], bf[2], bf[3],
                       ldV + bufb + (unsigned)(kv * 16 * TSTR * 2) + np * 32);
                mma16816(ofrag[2 * np],     a, bf[0], bf[1]);
                mma16816(ofrag[2 * np + 1], a, bf[2], bf[3]);
            }
        }
        __syncthreads();
    }

    // ---- combine group heads + write fp16 ----
    const float inv0 = 1.0f / lrow[0];
    const float inv1 = 1.0f / lrow[1];
    if (hw == 1) {
        #pragma unroll
        for (int nt = 0; nt < 8; nt++) {
            Obuf[(wr + er) * 66 + nt * 8 + ec]         = ofrag[nt][0] * inv0;
            Obuf[(wr + er) * 66 + nt * 8 + ec + 1]     = ofrag[nt][1] * inv0;
            Obuf[(wr + er + 8) * 66 + nt * 8 + ec]     = ofrag[nt][2] * inv1;
            Obuf[(wr + er + 8) * 66 + nt * 8 + ec + 1] = ofrag[nt][3] * inv1;
        }
    }
    __syncthreads();
    if (hw == 0) {
        size_t gr0 = (size_t)(b * NN + qt * 64 + wr + er) * (HH * DH_) + h * DH_;
        size_t gr1 = gr0 + 8 * (HH * DH_);
        #pragma unroll
        for (int nt = 0; nt < 8; nt++) {
            float o0 = ofrag[nt][0] * inv0 + Obuf[(wr + er) * 66 + nt * 8 + ec];
            float o1 = ofrag[nt][1] * inv0 + Obuf[(wr + er) * 66 + nt * 8 + ec + 1];
            float o2 = ofrag[nt][2] * inv1 + Obuf[(wr + er + 8) * 66 + nt * 8 + ec];
            float o3 = ofrag[nt][3] * inv1 + Obuf[(wr + er + 8) * 66 + nt * 8 + ec + 1];
            *(__half2*)(g_ah + gr0 + nt * 8 + ec) = __floats2half2_rn(o0, o1);
            *(__half2*)(g_ah + gr1 + nt * 8 + ec) = __floats2half2_rn(o2, o3);
        }
    }
}

// ---------------- launch ------------------------------------------------------
extern "C" void kernel_launch(void* const* d_in, const int* in_sizes, int n_in,
                              void* d_out, int out_size) {
    const float* tokens  = (const float*)d_in[0];
    const float* norm_w  = (const float*)d_in[1];
    const float* Wq      = (const float*)d_in[2];
    const float* Wkv     = (const float*)d_in[3];
    const float* Wout    = (const float*)d_in[4];
    const float* q_gamma = (const float*)d_in[5];
    const float* k_gamma = (const float*)d_in[6];
    float* out = (float*)d_out;

    __half *xh, *w, *wo, *ah;
    cudaGetSymbolAddress((void**)&xh, g_xh);
    cudaGetSymbolAddress((void**)&w,  g_w);
    cudaGetSymbolAddress((void**)&wo, g_wo);
    cudaGetSymbolAddress((void**)&ah, g_ah);

    dim3 tb(32, 8);
    wtransqkv_kernel<<<dim3(32, 32, 2), tb>>>(Wq, Wkv);
    wtrans_kernel<<<dim3(32, 16), tb>>>(Wout, wo, 512, 1024);

    rmsnorm_kernel<<<MM / 8, 256>>>(tokens, norm_w);

    cudaFuncSetAttribute(qkv_gemm_kernel,
                         cudaFuncAttributeMaxDynamicSharedMemorySize, GEMM_SMEM);
    cudaFuncSetAttribute(hgemm_kernel,
                         cudaFuncAttributeMaxDynamicSharedMemorySize, GEMM_SMEM);

    qkv_gemm_kernel<<<dim3(16, 32), 256, GEMM_SMEM>>>(xh, w, q_gamma, k_gamma);

    cudaFuncSetAttribute(attn_kernel, cudaFuncAttributeMaxDynamicSharedMemorySize,
                         ATT_SMEM);
    dim3 agrid(NN / 64, HH, BB);
    attn_kernel<<<agrid, 256, ATT_SMEM>>>();

    hgemm_kernel<<<dim3(8, 32), 256, GEMM_SMEM>>>(ah, wo, out, 512);
}

// round 10
// speedup vs baseline: 1.0815x; 1.0815x over previous
#include <cuda_runtime.h>
#include <cuda_fp16.h>
#include <cstdint>
#include <math.h>

#define BB 2
#define NN 2048
#define DD 1024
#define HH 8
#define QH_ 16
#define DH_ 64
#define MM (BB*NN)

// ---------------- scratch ----------------------------------------------------
__device__ __half g_xh [MM*DD];            // rmsnorm(x), fp16 [4096][1024]
__device__ __half g_w  [2*DD*DD];          // [Wq^T ; Wkv^T] fp16 [2048][1024]
__device__ __half g_wo [DD*HH*DH_];        // Wout^T fp16 [1024][512]
__device__ __half g_qh [BB*QH_*NN*DH_];    // normalized q fp16 [b][qh][n][dh]
__device__ __half g_kh [BB*HH*NN*DH_];     // normalized k fp16 [b][h][n][dh]
__device__ __half g_vh [BB*HH*NN*DH_];     // v fp16           [b][h][n][dh]
__device__ __half g_ah [MM*HH*DH_];        // group-summed attn out fp16 [4096][512]

// ---------------- mma / ldmatrix / cp.async helpers ---------------------------
__device__ __forceinline__ void ldsm4(unsigned& r0, unsigned& r1, unsigned& r2,
                                      unsigned& r3, unsigned addr) {
    asm volatile("ldmatrix.sync.aligned.m8n8.x4.shared.b16 {%0,%1,%2,%3}, [%4];"
                 : "=r"(r0), "=r"(r1), "=r"(r2), "=r"(r3) : "r"(addr));
}
__device__ __forceinline__ void ldsm4t(unsigned& r0, unsigned& r1, unsigned& r2,
                                       unsigned& r3, unsigned addr) {
    asm volatile("ldmatrix.sync.aligned.m8n8.x4.trans.shared.b16 {%0,%1,%2,%3}, [%4];"
                 : "=r"(r0), "=r"(r1), "=r"(r2), "=r"(r3) : "r"(addr));
}
__device__ __forceinline__ void mma16816(float* c, const unsigned* a,
                                         unsigned b0, unsigned b1) {
    asm volatile(
        "mma.sync.aligned.m16n8k16.row.col.f32.f16.f16.f32 "
        "{%0,%1,%2,%3},{%4,%5,%6,%7},{%8,%9},{%0,%1,%2,%3};"
        : "+f"(c[0]), "+f"(c[1]), "+f"(c[2]), "+f"(c[3])
        : "r"(a[0]), "r"(a[1]), "r"(a[2]), "r"(a[3]), "r"(b0), "r"(b1));
}
__device__ __forceinline__ void cpa16(unsigned dst, const void* src) {
    asm volatile("cp.async.cg.shared.global [%0], [%1], 16;" :: "r"(dst), "l"(src));
}
#define CP_COMMIT() asm volatile("cp.async.commit_group;")
#define CP_WAIT(n)  asm volatile("cp.async.wait_group %0;" :: "n"(n))

// ---------------- rmsnorm -> fp16, one warp per row ---------------------------
__global__ void rmsnorm_kernel(const float* __restrict__ x,
                               const float* __restrict__ w) {
    const int row = blockIdx.x * 8 + (threadIdx.x >> 5);
    const int lane = threadIdx.x & 31;
    const float4* xr = (const float4*)(x + (size_t)row * DD);
    float4 xv[8];
    float ss = 0.f;
    #pragma unroll
    for (int i = 0; i < 8; i++) {
        xv[i] = xr[lane + 32 * i];
        ss += xv[i].x * xv[i].x + xv[i].y * xv[i].y
            + xv[i].z * xv[i].z + xv[i].w * xv[i].w;
    }
    #pragma unroll
    for (int o = 16; o; o >>= 1) ss += __shfl_xor_sync(~0u, ss, o);
    const float r = rsqrtf(ss * (1.0f / DD) + 1.1920929e-07f);
    const float4* wr = (const float4*)w;
    uint2* yr = (uint2*)(g_xh + (size_t)row * DD);
    #pragma unroll
    for (int i = 0; i < 8; i++) {
        float4 wv = wr[lane + 32 * i];
        __half2 h0 = __floats2half2_rn(xv[i].x * r * wv.x, xv[i].y * r * wv.y);
        __half2 h1 = __floats2half2_rn(xv[i].z * r * wv.z, xv[i].w * r * wv.w);
        uint2 u;
        u.x = *(unsigned*)&h0;
        u.y = *(unsigned*)&h1;
        yr[lane + 32 * i] = u;
    }
}

// ---------------- weight transpose+convert -----------------------------------
__global__ void wtransqkv_kernel(const float* __restrict__ Wq,
                                 const float* __restrict__ Wkv) {
    __shared__ float t[32][33];
    const float* W = blockIdx.z ? Wkv : Wq;
    __half* Wt = g_w + (size_t)blockIdx.z * DD * DD;
    int n0 = blockIdx.x * 32, k0 = blockIdx.y * 32;
    int x = threadIdx.x, y = threadIdx.y;
    #pragma unroll
    for (int i = 0; i < 32; i += 8)
        t[y + i][x] = W[(size_t)(k0 + y + i) * DD + n0 + x];
    __syncthreads();
    #pragma unroll
    for (int i = 0; i < 32; i += 8)
        Wt[(size_t)(n0 + y + i) * DD + k0 + x] = __float2half(t[x][y + i]);
}
__global__ void wtrans_kernel(const float* __restrict__ W, __half* __restrict__ Wt,
                              int K, int N) {
    __shared__ float t[32][33];
    int n0 = blockIdx.x * 32, k0 = blockIdx.y * 32;
    int x = threadIdx.x, y = threadIdx.y;
    #pragma unroll
    for (int i = 0; i < 32; i += 8)
        t[y + i][x] = W[(size_t)(k0 + y + i) * N + n0 + x];
    __syncthreads();
    #pragma unroll
    for (int i = 0; i < 32; i += 8)
        Wt[(size_t)(n0 + y + i) * K + k0 + x] = __float2half(t[x][y + i]);
}

#define ASTR 40
#define ABUF (128*ASTR)

// ---------------- fused QKV GEMM + per-head norm epilogue (R8 2-stage) -------
__global__ void __launch_bounds__(256, 2)
qkv_gemm_kernel(const __half* __restrict__ A, const __half* __restrict__ Bt,
                const float* __restrict__ q_gamma,
                const float* __restrict__ k_gamma) {
    __shared__ __half sh[4 * ABUF];
    const int K = 1024;
    const int tid = threadIdx.x;
    const int lane = tid & 31;
    const int warp = tid >> 5;
    const int wm = (warp >> 1) << 5;
    const int wn = (warp & 1) << 6;
    const int bm = blockIdx.y << 7;
    const int bn = blockIdx.x << 7;

    const int lr = tid >> 2;
    const int lg = (tid & 3) << 3;
    const __half* Ag = A + (size_t)(bm + lr) * K + lg;
    const __half* Bg = Bt + (size_t)(bn + lr) * K + lg;
    const size_t rowskip = (size_t)64 * K;

    unsigned sb;
    asm("{ .reg .u64 t; cvta.to.shared.u64 t, %1; cvt.u32.u64 %0, t; }"
        : "=r"(sb) : "l"(sh));
    const unsigned stA0 = sb + (unsigned)(lr * ASTR + lg) * 2u;
    const unsigned stA1 = sb + (unsigned)((lr + 64) * ASTR + lg) * 2u;
    const unsigned stB0 = stA0 + (unsigned)(2 * ABUF) * 2u;
    const unsigned stB1 = stA1 + (unsigned)(2 * ABUF) * 2u;

    const int aRow = wm + (lane & 15);
    const int aK   = (lane >> 4) << 3;
    const int bRow = wn + (lane & 7) + ((lane >> 4) << 3);
    const int bK   = ((lane >> 3) & 1) << 3;
    const unsigned ldA = sb + (unsigned)(aRow * ASTR + aK) * 2u;
    const unsigned ldB = sb + (unsigned)(2 * ABUF + bRow * ASTR + bK) * 2u;

    float acc[2][8][4];
    #pragma unroll
    for (int i = 0; i < 2; i++) {
        #pragma unroll
        for (int j = 0; j < 8; j++) {
            #pragma unroll
            for (int q = 0; q < 4; q++) acc[i][j][q] = 0.f;
        }
    }

    cpa16(stA0, Ag);
    cpa16(stA1, Ag + rowskip);
    cpa16(stB0, Bg);
    cpa16(stB1, Bg + rowskip);
    CP_COMMIT();

    const int nch = K >> 5;
    for (int c = 0; c < nch; c++) {
        CP_WAIT(0);
        __syncthreads();
        if (c + 1 < nch) {
            const unsigned nb = (unsigned)((c + 1) & 1) * (unsigned)(ABUF * 2);
            const __half* An = Ag + (c + 1) * 32;
            const __half* Bn = Bg + (c + 1) * 32;
            cpa16(stA0 + nb, An);
            cpa16(stA1 + nb, An + rowskip);
            cpa16(stB0 + nb, Bn);
            cpa16(stB1 + nb, Bn + rowskip);
            CP_COMMIT();
        }
        const unsigned bo = (unsigned)(c & 1) * (unsigned)(ABUF * 2);
        #pragma unroll
        for (int ks = 0; ks < 2; ks++) {
            unsigned a0r[4], a1r[4], b[4][4];
            ldsm4(a0r[0], a0r[1], a0r[2], a0r[3], ldA + bo + ks * 32);
            ldsm4(a1r[0], a1r[1], a1r[2], a1r[3],
                  ldA + bo + 16 * ASTR * 2 + ks * 32);
            #pragma unroll
            for (int p = 0; p < 4; p++)
                ldsm4(b[p][0], b[p][1], b[p][2], b[p][3],
                      ldB + bo + (unsigned)(p * 16 * ASTR * 2) + ks * 32);
            #pragma unroll
            for (int p = 0; p < 4; p++) {
                mma16816(acc[0][2 * p],     a0r, b[p][0], b[p][1]);
                mma16816(acc[0][2 * p + 1], a0r, b[p][2], b[p][3]);
                mma16816(acc[1][2 * p],     a1r, b[p][0], b[p][1]);
                mma16816(acc[1][2 * p + 1], a1r, b[p][2], b[p][3]);
            }
        }
    }

    // ---- fused epilogue: per-head l2norm / convert ----
    const int er = lane >> 2;
    const int ec = (lane & 3) << 1;
    const int colbase = bn + wn;
    int head, nh;
    __half* darr;
    const float* gp;
    if (colbase < 1024)      { head = colbase >> 6;          darr = g_qh; gp = q_gamma + head * 64; nh = 16; }
    else if (colbase < 1536) { head = (colbase - 1024) >> 6; darr = g_kh; gp = k_gamma + head * 64; nh = 8; }
    else                     { head = (colbase - 1536) >> 6; darr = g_vh; gp = nullptr;             nh = 8; }

    float gs[8][2];
    #pragma unroll
    for (int nt = 0; nt < 8; nt++) {
        if (gp) {
            gs[nt][0] = (gp[nt * 8 + ec] + 1.f) * 8.f;
            gs[nt][1] = (gp[nt * 8 + ec + 1] + 1.f) * 8.f;
        } else {
            gs[nt][0] = 1.f;
            gs[nt][1] = 1.f;
        }
    }

    #pragma unroll
    for (int mt = 0; mt < 2; mt++) {
        #pragma unroll
        for (int rh = 0; rh < 2; rh++) {
            float s = 0.f;
            #pragma unroll
            for (int nt = 0; nt < 8; nt++) {
                float v0 = acc[mt][nt][2 * rh];
                float v1 = acc[mt][nt][2 * rh + 1];
                s = fmaf(v0, v0, fmaf(v1, v1, s));
            }
            s += __shfl_xor_sync(~0u, s, 1);
            s += __shfl_xor_sync(~0u, s, 2);
            float iv = gp ? (1.0f / fmaxf(sqrtf(s), 1e-12f)) : 1.0f;

            int m = bm + wm + mt * 16 + rh * 8 + er;
            int b = m >> 11, n = m & (NN - 1);
            __half* drow = darr + (((size_t)(b * nh + head)) * NN + n) * DH_;
            #pragma unroll
            for (int nt = 0; nt < 8; nt++) {
                float o0 = acc[mt][nt][2 * rh] * iv * gs[nt][0];
                float o1 = acc[mt][nt][2 * rh + 1] * iv * gs[nt][1];
                *(__half2*)(drow + nt * 8 + ec) = __floats2half2_rn(o0, o1);
            }
        }
    }
}

// ---------------- out-proj GEMM (R8 2-stage cp.async) -------------------------
__global__ void __launch_bounds__(256, 2)
hgemm_kernel(const __half* __restrict__ A, const __half* __restrict__ Bt,
             float* __restrict__ C, int K) {
    __shared__ __half sh[4 * ABUF];
    const int tid = threadIdx.x;
    const int lane = tid & 31;
    const int warp = tid >> 5;
    const int wm = (warp >> 1) << 5;
    const int wn = (warp & 1) << 6;
    const int bm = blockIdx.y << 7;
    const int bn = blockIdx.x << 7;

    const int lr = tid >> 2;
    const int lg = (tid & 3) << 3;
    const __half* Ag = A + (size_t)(bm + lr) * K + lg;
    const __half* Bg = Bt + (size_t)(bn + lr) * K + lg;
    const size_t rowskip = (size_t)64 * K;

    unsigned sb;
    asm("{ .reg .u64 t; cvta.to.shared.u64 t, %1; cvt.u32.u64 %0, t; }"
        : "=r"(sb) : "l"(sh));
    const unsigned stA0 = sb + (unsigned)(lr * ASTR + lg) * 2u;
    const unsigned stA1 = sb + (unsigned)((lr + 64) * ASTR + lg) * 2u;
    const unsigned stB0 = stA0 + (unsigned)(2 * ABUF) * 2u;
    const unsigned stB1 = stA1 + (unsigned)(2 * ABUF) * 2u;

    const int aRow = wm + (lane & 15);
    const int aK   = (lane >> 4) << 3;
    const int bRow = wn + (lane & 7) + ((lane >> 4) << 3);
    const int bK   = ((lane >> 3) & 1) << 3;
    const unsigned ldA = sb + (unsigned)(aRow * ASTR + aK) * 2u;
    const unsigned ldB = sb + (unsigned)(2 * ABUF + bRow * ASTR + bK) * 2u;

    float acc[2][8][4];
    #pragma unroll
    for (int i = 0; i < 2; i++) {
        #pragma unroll
        for (int j = 0; j < 8; j++) {
            #pragma unroll
            for (int q = 0; q < 4; q++) acc[i][j][q] = 0.f;
        }
    }

    cpa16(stA0, Ag);
    cpa16(stA1, Ag + rowskip);
    cpa16(stB0, Bg);
    cpa16(stB1, Bg + rowskip);
    CP_COMMIT();

    const int nch = K >> 5;
    for (int c = 0; c < nch; c++) {
        CP_WAIT(0);
        __syncthreads();
        if (c + 1 < nch) {
            const unsigned nb = (unsigned)((c + 1) & 1) * (unsigned)(ABUF * 2);
            const __half* An = Ag + (c + 1) * 32;
            const __half* Bn = Bg + (c + 1) * 32;
            cpa16(stA0 + nb, An);
            cpa16(stA1 + nb, An + rowskip);
            cpa16(stB0 + nb, Bn);
            cpa16(stB1 + nb, Bn + rowskip);
            CP_COMMIT();
        }
        const unsigned bo = (unsigned)(c & 1) * (unsigned)(ABUF * 2);
        #pragma unroll
        for (int ks = 0; ks < 2; ks++) {
            unsigned a0r[4], a1r[4], b[4][4];
            ldsm4(a0r[0], a0r[1], a0r[2], a0r[3], ldA + bo + ks * 32);
            ldsm4(a1r[0], a1r[1], a1r[2], a1r[3],
                  ldA + bo + 16 * ASTR * 2 + ks * 32);
            #pragma unroll
            for (int p = 0; p < 4; p++)
                ldsm4(b[p][0], b[p][1], b[p][2], b[p][3],
                      ldB + bo + (unsigned)(p * 16 * ASTR * 2) + ks * 32);
            #pragma unroll
            for (int p = 0; p < 4; p++) {
                mma16816(acc[0][2 * p],     a0r, b[p][0], b[p][1]);
                mma16816(acc[0][2 * p + 1], a0r, b[p][2], b[p][3]);
                mma16816(acc[1][2 * p],     a1r, b[p][0], b[p][1]);
                mma16816(acc[1][2 * p + 1], a1r, b[p][2], b[p][3]);
            }
        }
    }

    const int er = lane >> 2;
    const int ec = (lane & 3) << 1;
    #pragma unroll
    for (int mt = 0; mt < 2; mt++) {
        #pragma unroll
        for (int nt = 0; nt < 8; nt++) {
            int r0 = bm + wm + mt * 16 + er;
            int c0 = bn + wn + nt * 8 + ec;
            *(float2*)&C[(size_t)r0 * 1024 + c0] =
                make_float2(acc[mt][nt][0], acc[mt][nt][1]);
            *(float2*)&C[(size_t)(r0 + 8) * 1024 + c0] =
                make_float2(acc[mt][nt][2], acc[mt][nt][3]);
        }
    }
}

// ---------------- tensor-core flash attention ---------------------------------
// Softcap bounds logits to <= 6.25 -> EXACT fixed-max softmax (m == 6.25):
//   p = exp(6.25*tanh(0.02 s) - 6.25) = exp(-12.5 / (exp(0.04 s) + 1))
// No running max, no alpha rescale. Softcap math identical to R8.
#define TSTR 72
#define QOFF 0
#define KOFF 9216
#define VOFF 18432
#define ATT_SMEM (27648 * 2)

__global__ void __launch_bounds__(256) attn_kernel() {
    extern __shared__ __half sh[];
    float* Obuf = (float*)(sh + KOFF);
    const int qt = 31 - blockIdx.x;          // heavy tiles first
    const int h = blockIdx.y, b = blockIdx.z;
    const int tid = threadIdx.x, lane = tid & 31, warp = tid >> 5;
    const int hw = warp >> 2;
    const int wr = (warp & 3) << 4;
    const int er = lane >> 2, ec = (lane & 3) << 1;

    unsigned sb;
    asm("{ .reg .u64 t; cvta.to.shared.u64 t, %1; cvt.u32.u64 %0, t; }"
        : "=r"(sb) : "l"(sh));

    const __half* qg = g_qh + (((size_t)(b * QH_ + 2 * h)) * NN + qt * 64) * DH_;
    const __half* kg = g_kh + ((size_t)(b * HH + h)) * NN * DH_;
    const __half* vg = g_vh + ((size_t)(b * HH + h)) * NN * DH_;

    #pragma unroll
    for (int it = 0; it < 4; it++) {
        int u = tid + it * 256;
        int head = u >> 9, row = (u >> 3) & 63, cg = u & 7;
        cpa16(sb + (unsigned)(QOFF + head * 4608 + row * TSTR + cg * 8) * 2u,
              qg + (size_t)head * NN * DH_ + row * 64 + cg * 8);
    }
    {
        int row = tid >> 3, cg = tid & 7;
        #pragma unroll
        for (int it = 0; it < 2; it++) {
            int rr = row + it * 32;
            size_t go = (size_t)rr * 64 + cg * 8;
            cpa16(sb + (unsigned)(KOFF + rr * TSTR + cg * 8) * 2u, kg + go);
            cpa16(sb + (unsigned)(VOFF + rr * TSTR + cg * 8) * 2u, vg + go);
        }
    }
    CP_COMMIT();

    const unsigned ldQ = sb + (unsigned)(QOFF + hw * 4608 + (wr + (lane & 15)) * TSTR
                                         + ((lane >> 4) << 3)) * 2u;
    const unsigned ldK = sb + (unsigned)(KOFF + ((lane & 7) + ((lane >> 4) << 3)) * TSTR
                                         + (((lane >> 3) & 1) << 3)) * 2u;
    const unsigned ldV = sb + (unsigned)(VOFF + ((lane & 7) + (((lane >> 3) & 1) << 3)) * TSTR
                                         + ((lane >> 4) << 3)) * 2u;

    float ofrag[8][4];
    float lrow[2] = {0.f, 0.f};
    #pragma unroll
    for (int nt = 0; nt < 8; nt++) {
        #pragma unroll
        for (int q = 0; q < 4; q++) ofrag[nt][q] = 0.f;
    }

    for (int jt = 0; jt <= qt; jt++) {
        const unsigned bufb = (unsigned)(jt & 1) * 9216u;
        if (jt < qt) {
            const unsigned nb = (unsigned)((jt + 1) & 1) * 4608u;
            int row = tid >> 3, cg = tid & 7;
            #pragma unroll
            for (int it = 0; it < 2; it++) {
                int rr = row + it * 32;
                size_t go = (size_t)((jt + 1) * 64 + rr) * 64 + cg * 8;
                cpa16(sb + (KOFF + nb + rr * TSTR + cg * 8) * 2u, kg + go);
                cpa16(sb + (VOFF + nb + rr * TSTR + cg * 8) * 2u, vg + go);
            }
            CP_COMMIT();
            CP_WAIT(1);
        } else {
            CP_WAIT(0);
        }
        __syncthreads();

        // ---- S = Q @ K^T ----
        float sfrag[8][4];
        #pragma unroll
        for (int nt = 0; nt < 8; nt++) {
            #pragma unroll
            for (int q = 0; q < 4; q++) sfrag[nt][q] = 0.f;
        }
        #pragma unroll
        for (int ks = 0; ks < 4; ks++) {
            unsigned a[4];
            ldsm4(a[0], a[1], a[2], a[3], ldQ + ks * 32);
            #pragma unroll
            for (int np = 0; np < 4; np++) {
                unsigned bf[4];
                ldsm4(bf[0], bf[1], bf[2], bf[3],
                      ldK + bufb + (unsigned)(np * 16 * TSTR * 2) + ks * 32);
                mma16816(sfrag[2 * np],     a, bf[0], bf[1]);
                mma16816(sfrag[2 * np + 1], a, bf[2], bf[3]);
            }
        }

        // ---- softcap + mask + fixed-max softmax (exact) ----
        const bool diag = (jt == qt);
        #pragma unroll
        for (int r2 = 0; r2 < 2; r2++) {
            const int ig = wr + er + 8 * r2;
            float ps = 0.f;
            #pragma unroll
            for (int nt = 0; nt < 8; nt++) {
                #pragma unroll
                for (int c = 0; c < 2; c++) {
                    float s = sfrag[nt][2 * r2 + c];
                    float e = __expf(s * 0.04f);
                    float p = __expf(__fdividef(-12.5f, e + 1.f));
                    if (diag && (nt * 8 + ec + c > ig)) p = 0.f;
                    sfrag[nt][2 * r2 + c] = p;
                    ps += p;
                }
            }
            ps += __shfl_xor_sync(~0u, ps, 1);
            ps += __shfl_xor_sync(~0u, ps, 2);
            lrow[r2] += ps;
        }

        unsigned pa[8][2];
        #pragma unroll
        for (int nt = 0; nt < 8; nt++) {
            __half2 h0 = __floats2half2_rn(sfrag[nt][0], sfrag[nt][1]);
            __half2 h1 = __floats2half2_rn(sfrag[nt][2], sfrag[nt][3]);
            pa[nt][0] = *(unsigned*)&h0;
            pa[nt][1] = *(unsigned*)&h1;
        }

        // ---- O += P @ V ----
        #pragma unroll
        for (int kv = 0; kv < 4; kv++) {
            unsigned a[4] = {pa[2 * kv][0], pa[2 * kv][1],
                             pa[2 * kv + 1][0], pa[2 * kv + 1][1]};
            #pragma unroll
            for (int np = 0; np < 4; np++) {
                unsigned bf[4];
                ldsm4t(bf[0], bf[1], bf[2], bf[3],
                       ldV + bufb + (unsigned)(kv * 16 * TSTR * 2) + np * 32);
                mma16816(ofrag[2 * np],     a, bf[0], bf[1]);
                mma16816(ofrag[2 * np + 1], a, bf[2], bf[3]);
            }
        }
        __syncthreads();
    }

    // ---- combine group heads + write fp16 ----
    const float inv0 = 1.0f / lrow[0];
    const float inv1 = 1.0f / lrow[1];
    if (hw == 1) {
        #pragma unroll
        for (int nt = 0; nt < 8; nt++) {
            Obuf[(wr + er) * 66 + nt * 8 + ec]         = ofrag[nt][0] * inv0;
            Obuf[(wr + er) * 66 + nt * 8 + ec + 1]     = ofrag[nt][1] * inv0;
            Obuf[(wr + er + 8) * 66 + nt * 8 + ec]     = ofrag[nt][2] * inv1;
            Obuf[(wr + er + 8) * 66 + nt * 8 + ec + 1] = ofrag[nt][3] * inv1;
        }
    }
    __syncthreads();
    if (hw == 0) {
        size_t gr0 = (size_t)(b * NN + qt * 64 + wr + er) * (HH * DH_) + h * DH_;
        size_t gr1 = gr0 + 8 * (HH * DH_);
        #pragma unroll
        for (int nt = 0; nt < 8; nt++) {
            float o0 = ofrag[nt][0] * inv0 + Obuf[(wr + er) * 66 + nt * 8 + ec];
            float o1 = ofrag[nt][1] * inv0 + Obuf[(wr + er) * 66 + nt * 8 + ec + 1];
            float o2 = ofrag[nt][2] * inv1 + Obuf[(wr + er + 8) * 66 + nt * 8 + ec];
            float o3 = ofrag[nt][3] * inv1 + Obuf[(wr + er + 8) * 66 + nt * 8 + ec + 1];
            *(__half2*)(g_ah + gr0 + nt * 8 + ec) = __floats2half2_rn(o0, o1);
            *(__half2*)(g_ah + gr1 + nt * 8 + ec) = __floats2half2_rn(o2, o3);
        }
    }
}

// ---------------- launch ------------------------------------------------------
extern "C" void kernel_launch(void* const* d_in, const int* in_sizes, int n_in,
                              void* d_out, int out_size) {
    const float* tokens  = (const float*)d_in[0];
    const float* norm_w  = (const float*)d_in[1];
    const float* Wq      = (const float*)d_in[2];
    const float* Wkv     = (const float*)d_in[3];
    const float* Wout    = (const float*)d_in[4];
    const float* q_gamma = (const float*)d_in[5];
    const float* k_gamma = (const float*)d_in[6];
    float* out = (float*)d_out;

    __half *xh, *w, *wo, *ah;
    cudaGetSymbolAddress((void**)&xh, g_xh);
    cudaGetSymbolAddress((void**)&w,  g_w);
    cudaGetSymbolAddress((void**)&wo, g_wo);
    cudaGetSymbolAddress((void**)&ah, g_ah);

    dim3 tb(32, 8);
    wtransqkv_kernel<<<dim3(32, 32, 2), tb>>>(Wq, Wkv);
    wtrans_kernel<<<dim3(32, 16), tb>>>(Wout, wo, 512, 1024);

    rmsnorm_kernel<<<MM / 8, 256>>>(tokens, norm_w);

    qkv_gemm_kernel<<<dim3(16, 32), 256>>>(xh, w, q_gamma, k_gamma);

    cudaFuncSetAttribute(attn_kernel, cudaFuncAttributeMaxDynamicSharedMemorySize,
                         ATT_SMEM);
    dim3 agrid(NN / 64, HH, BB);
    attn_kernel<<<agrid, 256, ATT_SMEM>>>();

    hgemm_kernel<<<dim3(8, 32), 256>>>(ah, wo, out, 512);
}

// round 11
// speedup vs baseline: 1.1204x; 1.0359x over previous
#include <cuda_runtime.h>
#include <cuda_fp16.h>
#include <cstdint>
#include <math.h>

#define BB 2
#define NN 2048
#define DD 1024
#define HH 8
#define QH_ 16
#define DH_ 64
#define MM (BB*NN)

// ---------------- scratch ----------------------------------------------------
__device__ __half g_xh [MM*DD];            // rmsnorm(x), fp16 [4096][1024]
__device__ __half g_w  [2*DD*DD];          // [Wq^T ; Wkv^T] fp16 [2048][1024]
__device__ __half g_wo [DD*HH*DH_];        // Wout^T fp16 [1024][512]
__device__ __half g_qh [BB*QH_*NN*DH_];    // normalized q fp16 [b][qh][n][dh]
__device__ __half g_kh [BB*HH*NN*DH_];     // normalized k fp16 [b][h][n][dh]
__device__ __half g_vh [BB*HH*NN*DH_];     // v fp16           [b][h][n][dh]
__device__ __half g_ah [MM*HH*DH_];        // group-summed attn out fp16 [4096][512]

// ---------------- mma / ldmatrix / cp.async helpers ---------------------------
__device__ __forceinline__ void ldsm4(unsigned& r0, unsigned& r1, unsigned& r2,
                                      unsigned& r3, unsigned addr) {
    asm volatile("ldmatrix.sync.aligned.m8n8.x4.shared.b16 {%0,%1,%2,%3}, [%4];"
                 : "=r"(r0), "=r"(r1), "=r"(r2), "=r"(r3) : "r"(addr));
}
__device__ __forceinline__ void ldsm4t(unsigned& r0, unsigned& r1, unsigned& r2,
                                       unsigned& r3, unsigned addr) {
    asm volatile("ldmatrix.sync.aligned.m8n8.x4.trans.shared.b16 {%0,%1,%2,%3}, [%4];"
                 : "=r"(r0), "=r"(r1), "=r"(r2), "=r"(r3) : "r"(addr));
}
__device__ __forceinline__ void mma16816(float* c, const unsigned* a,
                                         unsigned b0, unsigned b1) {
    asm volatile(
        "mma.sync.aligned.m16n8k16.row.col.f32.f16.f16.f32 "
        "{%0,%1,%2,%3},{%4,%5,%6,%7},{%8,%9},{%0,%1,%2,%3};"
        : "+f"(c[0]), "+f"(c[1]), "+f"(c[2]), "+f"(c[3])
        : "r"(a[0]), "r"(a[1]), "r"(a[2]), "r"(a[3]), "r"(b0), "r"(b1));
}
__device__ __forceinline__ void cpa16(unsigned dst, const void* src) {
    asm volatile("cp.async.cg.shared.global [%0], [%1], 16;" :: "r"(dst), "l"(src));
}
#define CP_COMMIT() asm volatile("cp.async.commit_group;")
#define CP_WAIT(n)  asm volatile("cp.async.wait_group %0;" :: "n"(n))

// ---------------- fused prep: rmsnorm + all weight transposes -----------------
// blocks [0,512):     rmsnorm (8 rows per block, warp per row)
// blocks [512,2560):  Wq/Wkv transpose -> g_w
// blocks [2560,3072): Wout transpose   -> g_wo
__global__ void __launch_bounds__(256)
prep_kernel(const float* __restrict__ tokens, const float* __restrict__ norm_w,
            const float* __restrict__ Wq, const float* __restrict__ Wkv,
            const float* __restrict__ Wout) {
    __shared__ float t[32][33];
    const int bid = blockIdx.x;
    const int tid = threadIdx.x;

    if (bid < 512) {
        // ---- rmsnorm -> fp16, one warp per row ----
        const int row = bid * 8 + (tid >> 5);
        const int lane = tid & 31;
        const float4* xr = (const float4*)(tokens + (size_t)row * DD);
        float4 xv[8];
        float ss = 0.f;
        #pragma unroll
        for (int i = 0; i < 8; i++) {
            xv[i] = xr[lane + 32 * i];
            ss += xv[i].x * xv[i].x + xv[i].y * xv[i].y
                + xv[i].z * xv[i].z + xv[i].w * xv[i].w;
        }
        #pragma unroll
        for (int o = 16; o; o >>= 1) ss += __shfl_xor_sync(~0u, ss, o);
        const float r = rsqrtf(ss * (1.0f / DD) + 1.1920929e-07f);
        const float4* wr = (const float4*)norm_w;
        uint2* yr = (uint2*)(g_xh + (size_t)row * DD);
        #pragma unroll
        for (int i = 0; i < 8; i++) {
            float4 wv = wr[lane + 32 * i];
            __half2 h0 = __floats2half2_rn(xv[i].x * r * wv.x, xv[i].y * r * wv.y);
            __half2 h1 = __floats2half2_rn(xv[i].z * r * wv.z, xv[i].w * r * wv.w);
            uint2 u;
            u.x = *(unsigned*)&h0;
            u.y = *(unsigned*)&h1;
            yr[lane + 32 * i] = u;
        }
        return;
    }

    const int x = tid & 31, y = tid >> 5;
    if (bid < 2560) {
        // ---- Wq/Wkv transpose: 1024x1024 each ----
        const int u = bid - 512;
        const int z = u >> 10;               // 0 = Wq, 1 = Wkv
        const int rem = u & 1023;
        const int n0 = (rem & 31) * 32;
        const int k0 = (rem >> 5) * 32;
        const float* W = z ? Wkv : Wq;
        __half* Wt = g_w + (size_t)z * DD * DD;
        #pragma unroll
        for (int i = 0; i < 32; i += 8)
            t[y + i][x] = W[(size_t)(k0 + y + i) * DD + n0 + x];
        __syncthreads();
        #pragma unroll
        for (int i = 0; i < 32; i += 8)
            Wt[(size_t)(n0 + y + i) * DD + k0 + x] = __float2half(t[x][y + i]);
        return;
    }

    {
        // ---- Wout transpose: [512][1024] -> [1024][512] ----
        const int u = bid - 2560;
        const int n0 = (u & 31) * 32;        // output-col index (N=1024)
        const int k0 = (u >> 5) * 32;        // K=512
        #pragma unroll
        for (int i = 0; i < 32; i += 8)
            t[y + i][x] = Wout[(size_t)(k0 + y + i) * 1024 + n0 + x];
        __syncthreads();
        #pragma unroll
        for (int i = 0; i < 32; i += 8)
            g_wo[(size_t)(n0 + y + i) * 512 + k0 + x] = __float2half(t[x][y + i]);
    }
}

#define ASTR 40
#define ABUF (128*ASTR)

// ---------------- fused QKV GEMM + per-head norm epilogue (R8 2-stage) -------
__global__ void __launch_bounds__(256, 2)
qkv_gemm_kernel(const __half* __restrict__ A, const __half* __restrict__ Bt,
                const float* __restrict__ q_gamma,
                const float* __restrict__ k_gamma) {
    __shared__ __half sh[4 * ABUF];
    const int K = 1024;
    const int tid = threadIdx.x;
    const int lane = tid & 31;
    const int warp = tid >> 5;
    const int wm = (warp >> 1) << 5;
    const int wn = (warp & 1) << 6;
    const int bm = blockIdx.y << 7;
    const int bn = blockIdx.x << 7;

    const int lr = tid >> 2;
    const int lg = (tid & 3) << 3;
    const __half* Ag = A + (size_t)(bm + lr) * K + lg;
    const __half* Bg = Bt + (size_t)(bn + lr) * K + lg;
    const size_t rowskip = (size_t)64 * K;

    unsigned sb;
    asm("{ .reg .u64 t; cvta.to.shared.u64 t, %1; cvt.u32.u64 %0, t; }"
        : "=r"(sb) : "l"(sh));
    const unsigned stA0 = sb + (unsigned)(lr * ASTR + lg) * 2u;
    const unsigned stA1 = sb + (unsigned)((lr + 64) * ASTR + lg) * 2u;
    const unsigned stB0 = stA0 + (unsigned)(2 * ABUF) * 2u;
    const unsigned stB1 = stA1 + (unsigned)(2 * ABUF) * 2u;

    const int aRow = wm + (lane & 15);
    const int aK   = (lane >> 4) << 3;
    const int bRow = wn + (lane & 7) + ((lane >> 4) << 3);
    const int bK   = ((lane >> 3) & 1) << 3;
    const unsigned ldA = sb + (unsigned)(aRow * ASTR + aK) * 2u;
    const unsigned ldB = sb + (unsigned)(2 * ABUF + bRow * ASTR + bK) * 2u;

    float acc[2][8][4];
    #pragma unroll
    for (int i = 0; i < 2; i++) {
        #pragma unroll
        for (int j = 0; j < 8; j++) {
            #pragma unroll
            for (int q = 0; q < 4; q++) acc[i][j][q] = 0.f;
        }
    }

    cpa16(stA0, Ag);
    cpa16(stA1, Ag + rowskip);
    cpa16(stB0, Bg);
    cpa16(stB1, Bg + rowskip);
    CP_COMMIT();

    const int nch = K >> 5;
    for (int c = 0; c < nch; c++) {
        CP_WAIT(0);
        __syncthreads();
        if (c + 1 < nch) {
            const unsigned nb = (unsigned)((c + 1) & 1) * (unsigned)(ABUF * 2);
            const __half* An = Ag + (c + 1) * 32;
            const __half* Bn = Bg + (c + 1) * 32;
            cpa16(stA0 + nb, An);
            cpa16(stA1 + nb, An + rowskip);
            cpa16(stB0 + nb, Bn);
            cpa16(stB1 + nb, Bn + rowskip);
            CP_COMMIT();
        }
        const unsigned bo = (unsigned)(c & 1) * (unsigned)(ABUF * 2);
        #pragma unroll
        for (int ks = 0; ks < 2; ks++) {
            unsigned a0r[4], a1r[4], b[4][4];
            ldsm4(a0r[0], a0r[1], a0r[2], a0r[3], ldA + bo + ks * 32);
            ldsm4(a1r[0], a1r[1], a1r[2], a1r[3],
                  ldA + bo + 16 * ASTR * 2 + ks * 32);
            #pragma unroll
            for (int p = 0; p < 4; p++)
                ldsm4(b[p][0], b[p][1], b[p][2], b[p][3],
                      ldB + bo + (unsigned)(p * 16 * ASTR * 2) + ks * 32);
            #pragma unroll
            for (int p = 0; p < 4; p++) {
                mma16816(acc[0][2 * p],     a0r, b[p][0], b[p][1]);
                mma16816(acc[0][2 * p + 1], a0r, b[p][2], b[p][3]);
                mma16816(acc[1][2 * p],     a1r, b[p][0], b[p][1]);
                mma16816(acc[1][2 * p + 1], a1r, b[p][2], b[p][3]);
            }
        }
    }

    // ---- fused epilogue: per-head l2norm / convert ----
    const int er = lane >> 2;
    const int ec = (lane & 3) << 1;
    const int colbase = bn + wn;
    int head, nh;
    __half* darr;
    const float* gp;
    if (colbase < 1024)      { head = colbase >> 6;          darr = g_qh; gp = q_gamma + head * 64; nh = 16; }
    else if (colbase < 1536) { head = (colbase - 1024) >> 6; darr = g_kh; gp = k_gamma + head * 64; nh = 8; }
    else                     { head = (colbase - 1536) >> 6; darr = g_vh; gp = nullptr;             nh = 8; }

    float gs[8][2];
    #pragma unroll
    for (int nt = 0; nt < 8; nt++) {
        if (gp) {
            gs[nt][0] = (gp[nt * 8 + ec] + 1.f) * 8.f;
            gs[nt][1] = (gp[nt * 8 + ec + 1] + 1.f) * 8.f;
        } else {
            gs[nt][0] = 1.f;
            gs[nt][1] = 1.f;
        }
    }

    #pragma unroll
    for (int mt = 0; mt < 2; mt++) {
        #pragma unroll
        for (int rh = 0; rh < 2; rh++) {
            float s = 0.f;
            #pragma unroll
            for (int nt = 0; nt < 8; nt++) {
                float v0 = acc[mt][nt][2 * rh];
                float v1 = acc[mt][nt][2 * rh + 1];
                s = fmaf(v0, v0, fmaf(v1, v1, s));
            }
            s += __shfl_xor_sync(~0u, s, 1);
            s += __shfl_xor_sync(~0u, s, 2);
            float iv = gp ? (1.0f / fmaxf(sqrtf(s), 1e-12f)) : 1.0f;

            int m = bm + wm + mt * 16 + rh * 8 + er;
            int b = m >> 11, n = m & (NN - 1);
            __half* drow = darr + (((size_t)(b * nh + head)) * NN + n) * DH_;
            #pragma unroll
            for (int nt = 0; nt < 8; nt++) {
                float o0 = acc[mt][nt][2 * rh] * iv * gs[nt][0];
                float o1 = acc[mt][nt][2 * rh + 1] * iv * gs[nt][1];
                *(__half2*)(drow + nt * 8 + ec) = __floats2half2_rn(o0, o1);
            }
        }
    }
}

// ---------------- out-proj GEMM (R8 2-stage cp.async) -------------------------
__global__ void __launch_bounds__(256, 2)
hgemm_kernel(const __half* __restrict__ A, const __half* __restrict__ Bt,
             float* __restrict__ C, int K) {
    __shared__ __half sh[4 * ABUF];
    const int tid = threadIdx.x;
    const int lane = tid & 31;
    const int warp = tid >> 5;
    const int wm = (warp >> 1) << 5;
    const int wn = (warp & 1) << 6;
    const int bm = blockIdx.y << 7;
    const int bn = blockIdx.x << 7;

    const int lr = tid >> 2;
    const int lg = (tid & 3) << 3;
    const __half* Ag = A + (size_t)(bm + lr) * K + lg;
    const __half* Bg = Bt + (size_t)(bn + lr) * K + lg;
    const size_t rowskip = (size_t)64 * K;

    unsigned sb;
    asm("{ .reg .u64 t; cvta.to.shared.u64 t, %1; cvt.u32.u64 %0, t; }"
        : "=r"(sb) : "l"(sh));
    const unsigned stA0 = sb + (unsigned)(lr * ASTR + lg) * 2u;
    const unsigned stA1 = sb + (unsigned)((lr + 64) * ASTR + lg) * 2u;
    const unsigned stB0 = stA0 + (unsigned)(2 * ABUF) * 2u;
    const unsigned stB1 = stA1 + (unsigned)(2 * ABUF) * 2u;

    const int aRow = wm + (lane & 15);
    const int aK   = (lane >> 4) << 3;
    const int bRow = wn + (lane & 7) + ((lane >> 4) << 3);
    const int bK   = ((lane >> 3) & 1) << 3;
    const unsigned ldA = sb + (unsigned)(aRow * ASTR + aK) * 2u;
    const unsigned ldB = sb + (unsigned)(2 * ABUF + bRow * ASTR + bK) * 2u;

    float acc[2][8][4];
    #pragma unroll
    for (int i = 0; i < 2; i++) {
        #pragma unroll
        for (int j = 0; j < 8; j++) {
            #pragma unroll
            for (int q = 0; q < 4; q++) acc[i][j][q] = 0.f;
        }
    }

    cpa16(stA0, Ag);
    cpa16(stA1, Ag + rowskip);
    cpa16(stB0, Bg);
    cpa16(stB1, Bg + rowskip);
    CP_COMMIT();

    const int nch = K >> 5;
    for (int c = 0; c < nch; c++) {
        CP_WAIT(0);
        __syncthreads();
        if (c + 1 < nch) {
            const unsigned nb = (unsigned)((c + 1) & 1) * (unsigned)(ABUF * 2);
            const __half* An = Ag + (c + 1) * 32;
            const __half* Bn = Bg + (c + 1) * 32;
            cpa16(stA0 + nb, An);
            cpa16(stA1 + nb, An + rowskip);
            cpa16(stB0 + nb, Bn);
            cpa16(stB1 + nb, Bn + rowskip);
            CP_COMMIT();
        }
        const unsigned bo = (unsigned)(c & 1) * (unsigned)(ABUF * 2);
        #pragma unroll
        for (int ks = 0; ks < 2; ks++) {
            unsigned a0r[4], a1r[4], b[4][4];
            ldsm4(a0r[0], a0r[1], a0r[2], a0r[3], ldA + bo + ks * 32);
            ldsm4(a1r[0], a1r[1], a1r[2], a1r[3],
                  ldA + bo + 16 * ASTR * 2 + ks * 32);
            #pragma unroll
            for (int p = 0; p < 4; p++)
                ldsm4(b[p][0], b[p][1], b[p][2], b[p][3],
                      ldB + bo + (unsigned)(p * 16 * ASTR * 2) + ks * 32);
            #pragma unroll
            for (int p = 0; p < 4; p++) {
                mma16816(acc[0][2 * p],     a0r, b[p][0], b[p][1]);
                mma16816(acc[0][2 * p + 1], a0r, b[p][2], b[p][3]);
                mma16816(acc[1][2 * p],     a1r, b[p][0], b[p][1]);
                mma16816(acc[1][2 * p + 1], a1r, b[p][2], b[p][3]);
            }
        }
    }

    const int er = lane >> 2;
    const int ec = (lane & 3) << 1;
    #pragma unroll
    for (int mt = 0; mt < 2; mt++) {
        #pragma unroll
        for (int nt = 0; nt < 8; nt++) {
            int r0 = bm + wm + mt * 16 + er;
            int c0 = bn + wn + nt * 8 + ec;
            *(float2*)&C[(size_t)r0 * 1024 + c0] =
                make_float2(acc[mt][nt][0], acc[mt][nt][1]);
            *(float2*)&C[(size_t)(r0 + 8) * 1024 + c0] =
                make_float2(acc[mt][nt][2], acc[mt][nt][3]);
        }
    }
}

// ---------------- tensor-core flash attention (fixed-max softmax) -------------
#define TSTR 72
#define QOFF 0
#define KOFF 9216
#define VOFF 18432
#define ATT_SMEM (27648 * 2)

__global__ void __launch_bounds__(256, 2) attn_kernel() {
    extern __shared__ __half sh[];
    float* Obuf = (float*)(sh + KOFF);
    const int qt = 31 - blockIdx.x;          // heavy tiles first
    const int h = blockIdx.y, b = blockIdx.z;
    const int tid = threadIdx.x, lane = tid & 31, warp = tid >> 5;
    const int hw = warp >> 2;
    const int wr = (warp & 3) << 4;
    const int er = lane >> 2, ec = (lane & 3) << 1;

    unsigned sb;
    asm("{ .reg .u64 t; cvta.to.shared.u64 t, %1; cvt.u32.u64 %0, t; }"
        : "=r"(sb) : "l"(sh));

    const __half* qg = g_qh + (((size_t)(b * QH_ + 2 * h)) * NN + qt * 64) * DH_;
    const __half* kg = g_kh + ((size_t)(b * HH + h)) * NN * DH_;
    const __half* vg = g_vh + ((size_t)(b * HH + h)) * NN * DH_;

    #pragma unroll
    for (int it = 0; it < 4; it++) {
        int u = tid + it * 256;
        int head = u >> 9, row = (u >> 3) & 63, cg = u & 7;
        cpa16(sb + (unsigned)(QOFF + head * 4608 + row * TSTR + cg * 8) * 2u,
              qg + (size_t)head * NN * DH_ + row * 64 + cg * 8);
    }
    {
        int row = tid >> 3, cg = tid & 7;
        #pragma unroll
        for (int it = 0; it < 2; it++) {
            int rr = row + it * 32;
            size_t go = (size_t)rr * 64 + cg * 8;
            cpa16(sb + (unsigned)(KOFF + rr * TSTR + cg * 8) * 2u, kg + go);
            cpa16(sb + (unsigned)(VOFF + rr * TSTR + cg * 8) * 2u, vg + go);
        }
    }
    CP_COMMIT();

    const unsigned ldQ = sb + (unsigned)(QOFF + hw * 4608 + (wr + (lane & 15)) * TSTR
                                         + ((lane >> 4) << 3)) * 2u;
    const unsigned ldK = sb + (unsigned)(KOFF + ((lane & 7) + ((lane >> 4) << 3)) * TSTR
                                         + (((lane >> 3) & 1) << 3)) * 2u;
    const unsigned ldV = sb + (unsigned)(VOFF + ((lane & 7) + (((lane >> 3) & 1) << 3)) * TSTR
                                         + ((lane >> 4) << 3)) * 2u;

    float ofrag[8][4];
    float lrow[2] = {0.f, 0.f};
    #pragma unroll
    for (int nt = 0; nt < 8; nt++) {
        #pragma unroll
        for (int q = 0; q < 4; q++) ofrag[nt][q] = 0.f;
    }

    for (int jt = 0; jt <= qt; jt++) {
        const unsigned bufb = (unsigned)(jt & 1) * 9216u;
        if (jt < qt) {
            const unsigned nb = (unsigned)((jt + 1) & 1) * 4608u;
            int row = tid >> 3, cg = tid & 7;
            #pragma unroll
            for (int it = 0; it < 2; it++) {
                int rr = row + it * 32;
                size_t go = (size_t)((jt + 1) * 64 + rr) * 64 + cg * 8;
                cpa16(sb + (KOFF + nb + rr * TSTR + cg * 8) * 2u, kg + go);
                cpa16(sb + (VOFF + nb + rr * TSTR + cg * 8) * 2u, vg + go);
            }
            CP_COMMIT();
            CP_WAIT(1);
        } else {
            CP_WAIT(0);
        }
        __syncthreads();

        // ---- S = Q @ K^T ----
        float sfrag[8][4];
        #pragma unroll
        for (int nt = 0; nt < 8; nt++) {
            #pragma unroll
            for (int q = 0; q < 4; q++) sfrag[nt][q] = 0.f;
        }
        #pragma unroll
        for (int ks = 0; ks < 4; ks++) {
            unsigned a[4];
            ldsm4(a[0], a[1], a[2], a[3], ldQ + ks * 32);
            #pragma unroll
            for (int np = 0; np < 4; np++) {
                unsigned bf[4];
                ldsm4(bf[0], bf[1], bf[2], bf[3],
                      ldK + bufb + (unsigned)(np * 16 * TSTR * 2) + ks * 32);
                mma16816(sfrag[2 * np],     a, bf[0], bf[1]);
                mma16816(sfrag[2 * np + 1], a, bf[2], bf[3]);
            }
        }

        // ---- softcap + mask + fixed-max softmax (exact) ----
        const bool diag = (jt == qt);
        #pragma unroll
        for (int r2 = 0; r2 < 2; r2++) {
            const int ig = wr + er + 8 * r2;
            float ps = 0.f;
            #pragma unroll
            for (int nt = 0; nt < 8; nt++) {
                #pragma unroll
                for (int c = 0; c < 2; c++) {
                    float s = sfrag[nt][2 * r2 + c];
                    float e = __expf(s * 0.04f);
                    float p = __expf(__fdividef(-12.5f, e + 1.f));
                    if (diag && (nt * 8 + ec + c > ig)) p = 0.f;
                    sfrag[nt][2 * r2 + c] = p;
                    ps += p;
                }
            }
            ps += __shfl_xor_sync(~0u, ps, 1);
            ps += __shfl_xor_sync(~0u, ps, 2);
            lrow[r2] += ps;
        }

        unsigned pa[8][2];
        #pragma unroll
        for (int nt = 0; nt < 8; nt++) {
            __half2 h0 = __floats2half2_rn(sfrag[nt][0], sfrag[nt][1]);
            __half2 h1 = __floats2half2_rn(sfrag[nt][2], sfrag[nt][3]);
            pa[nt][0] = *(unsigned*)&h0;
            pa[nt][1] = *(unsigned*)&h1;
        }

        // ---- O += P @ V ----
        #pragma unroll
        for (int kv = 0; kv < 4; kv++) {
            unsigned a[4] = {pa[2 * kv][0], pa[2 * kv][1],
                             pa[2 * kv + 1][0], pa[2 * kv + 1][1]};
            #pragma unroll
            for (int np = 0; np < 4; np++) {
                unsigned bf[4];
                ldsm4t(bf[0], bf[1], bf[2], bf[3],
                       ldV + bufb + (unsigned)(kv * 16 * TSTR * 2) + np * 32);
                mma16816(ofrag[2 * np],     a, bf[0], bf[1]);
                mma16816(ofrag[2 * np + 1], a, bf[2], bf[3]);
            }
        }
        __syncthreads();
    }

    // ---- combine group heads + write fp16 ----
    const float inv0 = 1.0f / lrow[0];
    const float inv1 = 1.0f / lrow[1];
    if (hw == 1) {
        #pragma unroll
        for (int nt = 0; nt < 8; nt++) {
            Obuf[(wr + er) * 66 + nt * 8 + ec]         = ofrag[nt][0] * inv0;
            Obuf[(wr + er) * 66 + nt * 8 + ec + 1]     = ofrag[nt][1] * inv0;
            Obuf[(wr + er + 8) * 66 + nt * 8 + ec]     = ofrag[nt][2] * inv1;
            Obuf[(wr + er + 8) * 66 + nt * 8 + ec + 1] = ofrag[nt][3] * inv1;
        }
    }
    __syncthreads();
    if (hw == 0) {
        size_t gr0 = (size_t)(b * NN + qt * 64 + wr + er) * (HH * DH_) + h * DH_;
        size_t gr1 = gr0 + 8 * (HH * DH_);
        #pragma unroll
        for (int nt = 0; nt < 8; nt++) {
            float o0 = ofrag[nt][0] * inv0 + Obuf[(wr + er) * 66 + nt * 8 + ec];
            float o1 = ofrag[nt][1] * inv0 + Obuf[(wr + er) * 66 + nt * 8 + ec + 1];
            float o2 = ofrag[nt][2] * inv1 + Obuf[(wr + er + 8) * 66 + nt * 8 + ec];
            float o3 = ofrag[nt][3] * inv1 + Obuf[(wr + er + 8) * 66 + nt * 8 + ec + 1];
            *(__half2*)(g_ah + gr0 + nt * 8 + ec) = __floats2half2_rn(o0, o1);
            *(__half2*)(g_ah + gr1 + nt * 8 + ec) = __floats2half2_rn(o2, o3);
        }
    }
}

// ---------------- launch ------------------------------------------------------
extern "C" void kernel_launch(void* const* d_in, const int* in_sizes, int n_in,
                              void* d_out, int out_size) {
    const float* tokens  = (const float*)d_in[0];
    const float* norm_w  = (const float*)d_in[1];
    const float* Wq      = (const float*)d_in[2];
    const float* Wkv     = (const float*)d_in[3];
    const float* Wout    = (const float*)d_in[4];
    const float* q_gamma = (const float*)d_in[5];
    const float* k_gamma = (const float*)d_in[6];
    float* out = (float*)d_out;

    __half *xh, *w, *wo, *ah;
    cudaGetSymbolAddress((void**)&xh, g_xh);
    cudaGetSymbolAddress((void**)&w,  g_w);
    cudaGetSymbolAddress((void**)&wo, g_wo);
    cudaGetSymbolAddress((void**)&ah, g_ah);

    // fused prep: rmsnorm + all weight transposes in one launch
    prep_kernel<<<3072, 256>>>(tokens, norm_w, Wq, Wkv, Wout);

    qkv_gemm_kernel<<<dim3(16, 32), 256>>>(xh, w, q_gamma, k_gamma);

    cudaFuncSetAttribute(attn_kernel, cudaFuncAttributeMaxDynamicSharedMemorySize,
                         ATT_SMEM);
    dim3 agrid(NN / 64, HH, BB);
    attn_kernel<<<agrid, 256, ATT_SMEM>>>();

    hgemm_kernel<<<dim3(8, 32), 256>>>(ah, wo, out, 512);
}